// round 6
// baseline (speedup 1.0000x reference)
#include <cuda_runtime.h>
#include <cstdint>

// ---------------------------------------------------------------------------
// out[i] = sum_{e: w_rows[e]==i} Param_W[w_params[e]] * x[w_cols[e]]
//          + Param_b[b_params[i]]
//
// N = 262144, E = 16.7M. Edge scatter is at the joint L1tex/LTS op-rate floor
// (R1/R4: L2 89.6%, ~128us). R5: remove the 5.7us serialized prologue by
// zero-initializing out (memsetAsync) and folding the bias gather into the
// same kernel as atomic adds — one launch, no ordering bubble.
// ---------------------------------------------------------------------------

__global__ void __launch_bounds__(256)
fused_scatter_kernel(const float* __restrict__ x,
                     const float* __restrict__ Param_W,
                     const float* __restrict__ Param_b,
                     const int4*  __restrict__ rows4,
                     const int4*  __restrict__ cols4,
                     const int4*  __restrict__ params4,
                     const int4*  __restrict__ b_params4,
                     float*       __restrict__ out,
                     int E4, int N4)
{
    int t = blockIdx.x * blockDim.x + threadIdx.x;

    if (t < E4) {
        // ---- edge quad (identical to the proven R1 shape) ----
        int4 r = __ldcs(&rows4[t]);
        int4 c = __ldcs(&cols4[t]);
        int4 p = __ldcs(&params4[t]);

        float v0 = __ldg(&Param_W[p.x]) * __ldg(&x[c.x]);
        float v1 = __ldg(&Param_W[p.y]) * __ldg(&x[c.y]);
        float v2 = __ldg(&Param_W[p.z]) * __ldg(&x[c.z]);
        float v3 = __ldg(&Param_W[p.w]) * __ldg(&x[c.w]);

        atomicAdd(&out[r.x], v0);
        atomicAdd(&out[r.y], v1);
        atomicAdd(&out[r.z], v2);
        atomicAdd(&out[r.w], v3);
    } else if (t < E4 + N4) {
        // ---- bias quad: out[i] += Param_b[b_params[i]] onto zeroed out ----
        int i = t - E4;
        int4 b = __ldcs(&b_params4[i]);
        int base = i * 4;
        atomicAdd(&out[base + 0], __ldg(&Param_b[b.x]));
        atomicAdd(&out[base + 1], __ldg(&Param_b[b.y]));
        atomicAdd(&out[base + 2], __ldg(&Param_b[b.z]));
        atomicAdd(&out[base + 3], __ldg(&Param_b[b.w]));
    }
}

// Scalar tails (E%4 or N%4 != 0 — not expected for this shape, but safe).
__global__ void edge_scatter_tail_kernel(const float* __restrict__ x,
                                         const float* __restrict__ Param_W,
                                         const int*   __restrict__ rows,
                                         const int*   __restrict__ cols,
                                         const int*   __restrict__ params,
                                         float*       __restrict__ out,
                                         int start, int E)
{
    int e = start + blockIdx.x * blockDim.x + threadIdx.x;
    if (e < E) {
        float v = __ldg(&Param_W[params[e]]) * __ldg(&x[cols[e]]);
        atomicAdd(&out[rows[e]], v);
    }
}

__global__ void bias_tail_kernel(const float* __restrict__ Param_b,
                                 const int*   __restrict__ b_params,
                                 float*       __restrict__ out,
                                 int start, int N)
{
    int i = start + blockIdx.x * blockDim.x + threadIdx.x;
    if (i < N) atomicAdd(&out[i], __ldg(&Param_b[b_params[i]]));
}

extern "C" void kernel_launch(void* const* d_in, const int* in_sizes, int n_in,
                              void* d_out, int out_size)
{
    const float* x        = (const float*)d_in[0];
    const float* Param_W  = (const float*)d_in[1];
    const float* Param_b  = (const float*)d_in[2];
    const int*   w_rows   = (const int*)  d_in[3];
    const int*   w_cols   = (const int*)  d_in[4];
    const int*   w_params = (const int*)  d_in[5];
    const int*   b_params = (const int*)  d_in[6];
    float*       out      = (float*)d_out;

    const int N = out_size;       // 262144
    const int E = in_sizes[3];    // 16777216

    // 1) Zero the output (atomics accumulate on top; also clears poison).
    cudaMemsetAsync(out, 0, (size_t)N * sizeof(float));

    // 2) One fused kernel: E/4 edge-quads + N/4 bias-quads.
    int E4 = E / 4;
    int N4 = N / 4;
    {
        int total   = E4 + N4;
        int threads = 256;
        int blocks  = (total + threads - 1) / threads;
        if (blocks > 0) {
            fused_scatter_kernel<<<blocks, threads>>>(
                x, Param_W, Param_b,
                (const int4*)w_rows, (const int4*)w_cols, (const int4*)w_params,
                (const int4*)b_params,
                out, E4, N4);
        }
    }

    // 3) Tails (skipped for this shape).
    int e_tail = E4 * 4;
    if (E - e_tail > 0) {
        edge_scatter_tail_kernel<<<1, 256>>>(
            x, Param_W, w_rows, w_cols, w_params, out, e_tail, E);
    }
    int n_tail = N4 * 4;
    if (N - n_tail > 0) {
        bias_tail_kernel<<<1, 256>>>(Param_b, b_params, out, n_tail, N);
    }
}